// round 2
// baseline (speedup 1.0000x reference)
#include <cuda_runtime.h>
#include <cuda_bf16.h>
#include <math.h>
#include <float.h>
#include <stdint.h>

#define BD 256      // batch
#define DD 4096     // dim

// Scratch (allocation-free: device globals)
__device__ __nv_bfloat16 g_Mhi[(size_t)DD * DD];   // bf16 hi of W + W^T (32MB)
__device__ __nv_bfloat16 g_Mlo[(size_t)DD * DD];   // bf16 residual      (32MB)
__device__ __nv_bfloat16 g_Xbf[(size_t)BD * DD];   // x in bf16 (exact: binary)
__device__ float         g_grad[(size_t)BD * DD];  // grad = 0.5(W+W^T)x + b

// ---------------------------------------------------------------------------
// Kernel 1: M = W + W^T, split into bf16 hi + bf16 lo. Each unordered tile
// pair (i,j)/(j,i) handled by one CTA so W is read exactly once.
// ---------------------------------------------------------------------------
__global__ void k_buildM(const float* __restrict__ W) {
    int bx = blockIdx.x, by = blockIdx.y;
    if (by > bx) return;            // only lower-left incl. diagonal
    __shared__ float t1[32][33];
    __shared__ float t2[32][33];
    int tx = threadIdx.x, ty = threadIdx.y;   // 32 x 8
    int r1 = by * 32, c1 = bx * 32;
    #pragma unroll
    for (int k = 0; k < 4; k++) {
        int i = ty + k * 8;
        t1[i][tx] = W[(size_t)(r1 + i) * DD + c1 + tx];
        t2[i][tx] = W[(size_t)(c1 + i) * DD + r1 + tx];
    }
    __syncthreads();
    #pragma unroll
    for (int k = 0; k < 4; k++) {
        int i = ty + k * 8;
        // output tile (r1, c1): M[r1+i][c1+tx] = W[r1+i][c1+tx] + W[c1+tx][r1+i]
        float m1 = t1[i][tx] + t2[tx][i];
        // output tile (c1, r1): M[c1+i][r1+tx] = W[c1+i][r1+tx] + W[r1+tx][c1+i]
        float m2 = t2[i][tx] + t1[tx][i];
        size_t o1 = (size_t)(r1 + i) * DD + c1 + tx;
        size_t o2 = (size_t)(c1 + i) * DD + r1 + tx;
        __nv_bfloat16 h1 = __float2bfloat16(m1);
        g_Mhi[o1] = h1;
        g_Mlo[o1] = __float2bfloat16(m1 - __bfloat162float(h1));
        __nv_bfloat16 h2 = __float2bfloat16(m2);
        g_Mhi[o2] = h2;
        g_Mlo[o2] = __float2bfloat16(m2 - __bfloat162float(h2));
    }
}

// ---------------------------------------------------------------------------
// Kernel 2: x -> bf16 (exact, x is 0/1)
// ---------------------------------------------------------------------------
__global__ void k_convX(const float* __restrict__ x) {
    int i = blockIdx.x * 256 + threadIdx.x;
    g_Xbf[i] = __float2bfloat16(x[i]);
}

// ---------------------------------------------------------------------------
// Kernel 3: GEMM  grad = 0.5 * (Xbf @ Mhi + Xbf @ Mlo) + bias
// BM=64, BN=64, BK=32; 128 threads (4 warps, warp tile 32x32), mma.m16n8k16.
// Grid: (4096/64, 256/64) = (64, 4) = 256 CTAs.
// ---------------------------------------------------------------------------
#define BM 64
#define BN 64
#define BK 32

__global__ __launch_bounds__(128) void k_gemm(const float* __restrict__ bias) {
    __shared__ __nv_bfloat16 sA[BM][40];   // [m][k], padded, 16B-aligned rows
    __shared__ __nv_bfloat16 sBh[BN][34];  // [n][k] (transposed on store)
    __shared__ __nv_bfloat16 sBl[BN][34];

    int tid  = threadIdx.x;
    int lane = tid & 31, w = tid >> 5;
    int m0 = blockIdx.y * BM;
    int n0 = blockIdx.x * BN;
    int wm = (w >> 1) * 32;     // warp row offset: 0 / 32
    int wn = (w & 1) * 32;      // warp col offset: 0 / 32

    float acc[2][4][4];
    #pragma unroll
    for (int a = 0; a < 2; a++)
        #pragma unroll
        for (int b = 0; b < 4; b++)
            #pragma unroll
            for (int c = 0; c < 4; c++) acc[a][b][c] = 0.f;

    int arow = tid >> 1;              // 0..63
    int acol = (tid & 1) * 16;        // 0 / 16
    int bk   = tid >> 2;              // 0..31
    int bn   = (tid & 3) * 16;        // 0,16,32,48

    for (int k0 = 0; k0 < DD; k0 += BK) {
        // --- load A tile (64x32) ---
        #pragma unroll
        for (int v = 0; v < 2; v++) {
            uint4 pa = *(const uint4*)&g_Xbf[(size_t)(m0 + arow) * DD + k0 + acol + v * 8];
            *(uint4*)&sA[arow][acol + v * 8] = pa;
        }
        // --- load B tiles (32x64 each), store transposed [n][k] ---
        #pragma unroll
        for (int v = 0; v < 2; v++) {
            uint4 ph = *(const uint4*)&g_Mhi[(size_t)(k0 + bk) * DD + n0 + bn + v * 8];
            uint4 pl = *(const uint4*)&g_Mlo[(size_t)(k0 + bk) * DD + n0 + bn + v * 8];
            const __nv_bfloat16* vh = (const __nv_bfloat16*)&ph;
            const __nv_bfloat16* vl = (const __nv_bfloat16*)&pl;
            #pragma unroll
            for (int j = 0; j < 8; j++) {
                sBh[bn + v * 8 + j][bk] = vh[j];
                sBl[bn + v * 8 + j][bk] = vl[j];
            }
        }
        __syncthreads();

        int r = lane >> 2, c = (lane & 3) * 2;
        #pragma unroll
        for (int ks = 0; ks < BK; ks += 16) {
            uint32_t af[2][4];
            #pragma unroll
            for (int mt = 0; mt < 2; mt++) {
                af[mt][0] = *(const uint32_t*)&sA[wm + mt * 16 + r    ][ks + c    ];
                af[mt][1] = *(const uint32_t*)&sA[wm + mt * 16 + r + 8][ks + c    ];
                af[mt][2] = *(const uint32_t*)&sA[wm + mt * 16 + r    ][ks + c + 8];
                af[mt][3] = *(const uint32_t*)&sA[wm + mt * 16 + r + 8][ks + c + 8];
            }
            #pragma unroll
            for (int nt = 0; nt < 4; nt++) {
                int n = wn + nt * 8 + (lane >> 2);
                uint32_t bh0 = *(const uint32_t*)&sBh[n][ks + c    ];
                uint32_t bh1 = *(const uint32_t*)&sBh[n][ks + c + 8];
                uint32_t bl0 = *(const uint32_t*)&sBl[n][ks + c    ];
                uint32_t bl1 = *(const uint32_t*)&sBl[n][ks + c + 8];
                #pragma unroll
                for (int mt = 0; mt < 2; mt++) {
                    asm volatile(
                        "mma.sync.aligned.m16n8k16.row.col.f32.bf16.bf16.f32 "
                        "{%0,%1,%2,%3}, {%4,%5,%6,%7}, {%8,%9}, {%0,%1,%2,%3};\n"
                        : "+f"(acc[mt][nt][0]), "+f"(acc[mt][nt][1]),
                          "+f"(acc[mt][nt][2]), "+f"(acc[mt][nt][3])
                        : "r"(af[mt][0]), "r"(af[mt][1]), "r"(af[mt][2]), "r"(af[mt][3]),
                          "r"(bh0), "r"(bh1));
                    asm volatile(
                        "mma.sync.aligned.m16n8k16.row.col.f32.bf16.bf16.f32 "
                        "{%0,%1,%2,%3}, {%4,%5,%6,%7}, {%8,%9}, {%0,%1,%2,%3};\n"
                        : "+f"(acc[mt][nt][0]), "+f"(acc[mt][nt][1]),
                          "+f"(acc[mt][nt][2]), "+f"(acc[mt][nt][3])
                        : "r"(af[mt][0]), "r"(af[mt][1]), "r"(af[mt][2]), "r"(af[mt][3]),
                          "r"(bl0), "r"(bl1));
                }
            }
        }
        __syncthreads();
    }

    // epilogue: grad = 0.5*acc + bias
    int r = lane >> 2, c2 = (lane & 3) * 2;
    #pragma unroll
    for (int mt = 0; mt < 2; mt++)
        #pragma unroll
        for (int nt = 0; nt < 4; nt++) {
            int grow = m0 + wm + mt * 16 + r;
            int gcol = n0 + wn + nt * 8 + c2;
            float b0v = bias[gcol], b1v = bias[gcol + 1];
            g_grad[(size_t)grow * DD + gcol]         = 0.5f * acc[mt][nt][0] + b0v;
            g_grad[(size_t)grow * DD + gcol + 1]     = 0.5f * acc[mt][nt][1] + b1v;
            g_grad[(size_t)(grow + 8) * DD + gcol]     = 0.5f * acc[mt][nt][2] + b0v;
            g_grad[(size_t)(grow + 8) * DD + gcol + 1] = 0.5f * acc[mt][nt][3] + b1v;
        }
}

// ---------------------------------------------------------------------------
// Kernel 4: per-row sampler. One CTA (256 thr) per sample row.
// log_acc = min(0.5*d^T W d + lse(scx) - lse(scy), 0); scy = scx with sign
// flipped at the top-`radius` Gumbel indices.
// ---------------------------------------------------------------------------
__global__ __launch_bounds__(256) void k_sample(
    const float* __restrict__ x, const float* __restrict__ W,
    const int* __restrict__ radius_raw, const float* __restrict__ gum,
    const float* __restrict__ u, float* __restrict__ out)
{
    int row = blockIdx.x;
    int tid = threadIdx.x;
    __shared__ float s_scx[DD];
    __shared__ float s_v[DD];
    __shared__ unsigned char s_flag[DD];
    __shared__ float red[256];
    __shared__ int   redi[256];
    __shared__ int   s_idx[16];

    const float* xr  = x    + (size_t)row * DD;
    const float* gr  = g_grad + (size_t)row * DD;
    const float* gur = gum  + (size_t)row * DD;

    // score_change_x and gumbel-perturbed keys
    for (int j = tid; j < DD; j += 256) {
        float xv  = xr[j];
        float gv  = gr[j];
        float scx = (0.5f - xv) * gv;          // (1-2x)*grad/2
        s_scx[j]  = scx;
        float uu  = gur[j];
        uu = fminf(fmaxf(uu, 1e-10f), 1.0f - 1e-10f);
        s_v[j]    = scx - logf(-logf(uu));     // + gumbel
        s_flag[j] = 0;
    }
    __syncthreads();

    // ---- lse_x ----
    float lmax = -FLT_MAX;
    for (int j = tid; j < DD; j += 256) lmax = fmaxf(lmax, s_scx[j]);
    red[tid] = lmax; __syncthreads();
    for (int s = 128; s > 0; s >>= 1) {
        if (tid < s) red[tid] = fmaxf(red[tid], red[tid + s]);
        __syncthreads();
    }
    float mx = red[0]; __syncthreads();
    float lsum = 0.f;
    for (int j = tid; j < DD; j += 256) lsum += expf(s_scx[j] - mx);
    red[tid] = lsum; __syncthreads();
    for (int s = 128; s > 0; s >>= 1) {
        if (tid < s) red[tid] += red[tid + s];
        __syncthreads();
    }
    float lse_x = mx + logf(red[0]); __syncthreads();

    // ---- top-`radius` via iterated argmax (radius <= 15) ----
    int radius = radius_raw[row] + 1;
    for (int t = 0; t < radius; t++) {
        float bv = -FLT_MAX; int bi = 0;
        for (int j = tid; j < DD; j += 256) {
            float v = s_v[j];
            if (v > bv) { bv = v; bi = j; }
        }
        red[tid] = bv; redi[tid] = bi; __syncthreads();
        for (int s = 128; s > 0; s >>= 1) {
            if (tid < s) {
                float v2 = red[tid + s]; int i2 = redi[tid + s];
                if (v2 > red[tid] || (v2 == red[tid] && i2 < redi[tid])) {
                    red[tid] = v2; redi[tid] = i2;
                }
            }
            __syncthreads();
        }
        if (tid == 0) { int b0 = redi[0]; s_idx[t] = b0; s_v[b0] = -FLT_MAX; }
        __syncthreads();
    }
    if (tid < radius) s_flag[s_idx[tid]] = 1;
    __syncthreads();

    // ---- quad = 0.5 * sum_{a,b} d_a d_b W[ia][ib] ----
    float q = 0.f;
    int rr = radius * radius;
    for (int p = tid; p < rr; p += 256) {
        int a = p / radius, bb = p % radius;
        int ia = s_idx[a], ib = s_idx[bb];
        float da = 1.f - 2.f * xr[ia];
        float db = 1.f - 2.f * xr[ib];
        q += da * db * W[(size_t)ia * DD + ib];
    }
    red[tid] = q; __syncthreads();
    for (int s = 128; s > 0; s >>= 1) {
        if (tid < s) red[tid] += red[tid + s];
        __syncthreads();
    }
    float quad = 0.5f * red[0]; __syncthreads();

    // ---- lse_y (sign-flipped at flipped positions) ----
    float lmax2 = -FLT_MAX;
    for (int j = tid; j < DD; j += 256) {
        float v = s_flag[j] ? -s_scx[j] : s_scx[j];
        lmax2 = fmaxf(lmax2, v);
    }
    red[tid] = lmax2; __syncthreads();
    for (int s = 128; s > 0; s >>= 1) {
        if (tid < s) red[tid] = fmaxf(red[tid], red[tid + s]);
        __syncthreads();
    }
    float mx2 = red[0]; __syncthreads();
    float lsum2 = 0.f;
    for (int j = tid; j < DD; j += 256) {
        float v = s_flag[j] ? -s_scx[j] : s_scx[j];
        lsum2 += expf(v - mx2);
    }
    red[tid] = lsum2; __syncthreads();
    for (int s = 128; s > 0; s >>= 1) {
        if (tid < s) red[tid] += red[tid + s];
        __syncthreads();
    }
    float lse_y = mx2 + logf(red[0]); __syncthreads();

    // ---- accept + write ----
    float la = quad + lse_x - lse_y;
    la = fminf(la, 0.f);
    int accept = (expf(la) > u[row]) ? 1 : 0;

    for (int j = tid; j < DD; j += 256) {
        float xv = xr[j];
        float yv = s_flag[j] ? (1.f - xv) : xv;
        out[(size_t)row * DD + j] = accept ? yv : xv;
    }
}

// ---------------------------------------------------------------------------
extern "C" void kernel_launch(void* const* d_in, const int* in_sizes, int n_in,
                              void* d_out, int out_size) {
    const float* x          = (const float*)d_in[0];
    const float* W          = (const float*)d_in[1];
    const float* bias       = (const float*)d_in[2];
    const int*   radius_raw = (const int*)d_in[3];
    const float* gum        = (const float*)d_in[4];
    const float* u          = (const float*)d_in[5];
    float* out = (float*)d_out;

    k_buildM<<<dim3(DD / 32, DD / 32), dim3(32, 8)>>>(W);
    k_convX<<<(BD * DD) / 256, 256>>>(x);
    k_gemm<<<dim3(DD / BN, BD / BM), 128>>>(bias);
    k_sample<<<BD, 256>>>(x, W, radius_raw, gum, u, out);
}

// round 3
// speedup vs baseline: 1.4328x; 1.4328x over previous
#include <cuda_runtime.h>
#include <cuda_bf16.h>
#include <math.h>
#include <float.h>
#include <stdint.h>

#define BD 256      // batch
#define DD 4096     // dim

// Scratch (allocation-free: device globals)
__device__ __nv_bfloat16 g_Mhi[(size_t)DD * DD];   // bf16 hi of W + W^T (32MB)
__device__ __nv_bfloat16 g_Mlo[(size_t)DD * DD];   // bf16 residual      (32MB)
__device__ __nv_bfloat16 g_Xbf[(size_t)BD * DD];   // x in bf16 (exact: binary)
__device__ float         g_grad[(size_t)BD * DD];  // grad = 0.5(W+W^T)x + b

// ---------------------------------------------------------------------------
// Kernel 1: M = W + W^T -> bf16 hi + bf16 lo. 64x64 tile pairs, W read once.
// float4 gmem loads, bf162 packed stores (full-width transactions).
// ---------------------------------------------------------------------------
__global__ __launch_bounds__(256) void k_buildM(const float* __restrict__ W) {
    int bx = blockIdx.x, by = blockIdx.y;
    if (by > bx) return;
    __shared__ float t1[64][65];
    __shared__ float t2[64][65];
    int tid = threadIdx.x;
    int r1 = by * 64, c1 = bx * 64;
    bool diag = (bx == by);

    #pragma unroll
    for (int i = 0; i < 4; i++) {
        int chunk = tid + i * 256;          // 0..1023
        int row = chunk >> 4;               // /16 float4 per row
        int c4  = (chunk & 15) * 4;
        float4 v1 = *(const float4*)&W[(size_t)(r1 + row) * DD + c1 + c4];
        t1[row][c4] = v1.x; t1[row][c4+1] = v1.y; t1[row][c4+2] = v1.z; t1[row][c4+3] = v1.w;
        if (!diag) {
            float4 v2 = *(const float4*)&W[(size_t)(c1 + row) * DD + r1 + c4];
            t2[row][c4] = v2.x; t2[row][c4+1] = v2.y; t2[row][c4+2] = v2.z; t2[row][c4+3] = v2.w;
        } else {
            t2[row][c4] = v1.x; t2[row][c4+1] = v1.y; t2[row][c4+2] = v1.z; t2[row][c4+3] = v1.w;
        }
    }
    __syncthreads();

    #pragma unroll
    for (int i = 0; i < 8; i++) {
        int pair = tid + i * 256;           // 0..2047
        int row = pair >> 5;                // 64 rows
        int cp  = pair & 31;                // 32 col-pairs
        // tile (r1, c1)
        {
            float a = t1[row][2*cp]   + t2[2*cp][row];
            float b = t1[row][2*cp+1] + t2[2*cp+1][row];
            size_t off = (size_t)(r1 + row) * DD + c1 + 2*cp;
            __nv_bfloat16 ha = __float2bfloat16(a), hb = __float2bfloat16(b);
            __nv_bfloat162 h; h.x = ha; h.y = hb;
            *(__nv_bfloat162*)&g_Mhi[off] = h;
            __nv_bfloat162 l;
            l.x = __float2bfloat16(a - __bfloat162float(ha));
            l.y = __float2bfloat16(b - __bfloat162float(hb));
            *(__nv_bfloat162*)&g_Mlo[off] = l;
        }
        if (!diag) {                         // tile (c1, r1)
            float a = t2[row][2*cp]   + t1[2*cp][row];
            float b = t2[row][2*cp+1] + t1[2*cp+1][row];
            size_t off = (size_t)(c1 + row) * DD + r1 + 2*cp;
            __nv_bfloat16 ha = __float2bfloat16(a), hb = __float2bfloat16(b);
            __nv_bfloat162 h; h.x = ha; h.y = hb;
            *(__nv_bfloat162*)&g_Mhi[off] = h;
            __nv_bfloat162 l;
            l.x = __float2bfloat16(a - __bfloat162float(ha));
            l.y = __float2bfloat16(b - __bfloat162float(hb));
            *(__nv_bfloat162*)&g_Mlo[off] = l;
        }
    }
}

// ---------------------------------------------------------------------------
// Kernel 2: x -> bf16 (exact: x is 0/1), vectorized
// ---------------------------------------------------------------------------
__global__ void k_convX(const float* __restrict__ x) {
    int i = (blockIdx.x * 256 + threadIdx.x) * 4;
    float4 v = *(const float4*)&x[i];
    __nv_bfloat162 p0; p0.x = __float2bfloat16(v.x); p0.y = __float2bfloat16(v.y);
    __nv_bfloat162 p1; p1.x = __float2bfloat16(v.z); p1.y = __float2bfloat16(v.w);
    *(__nv_bfloat162*)&g_Xbf[i]     = p0;
    *(__nv_bfloat162*)&g_Xbf[i + 2] = p1;
}

// ---------------------------------------------------------------------------
// Kernel 3: GEMM  grad = 0.5 * (Xbf @ Mhi + Xbf @ Mlo) + bias
// BM=64, BN=64, BK=32. cp.async double-buffered, ldmatrix fragments.
// ---------------------------------------------------------------------------
#define BM 64
#define BN 64
#define BK 32
#define NIT (DD / BK)

__device__ __forceinline__ void cp16(void* s, const void* g) {
    uint32_t sa = (uint32_t)__cvta_generic_to_shared(s);
    asm volatile("cp.async.cg.shared.global [%0], [%1], 16;\n" :: "r"(sa), "l"(g));
}
__device__ __forceinline__ void ldmx4(uint32_t* r, const void* p) {
    uint32_t a = (uint32_t)__cvta_generic_to_shared(p);
    asm volatile("ldmatrix.sync.aligned.m8n8.x4.shared.b16 {%0,%1,%2,%3}, [%4];\n"
                 : "=r"(r[0]), "=r"(r[1]), "=r"(r[2]), "=r"(r[3]) : "r"(a));
}
__device__ __forceinline__ void ldmx4t(uint32_t* r, const void* p) {
    uint32_t a = (uint32_t)__cvta_generic_to_shared(p);
    asm volatile("ldmatrix.sync.aligned.m8n8.x4.trans.shared.b16 {%0,%1,%2,%3}, [%4];\n"
                 : "=r"(r[0]), "=r"(r[1]), "=r"(r[2]), "=r"(r[3]) : "r"(a));
}
__device__ __forceinline__ void mma16816(float* d, const uint32_t* a, uint32_t b0, uint32_t b1) {
    asm volatile(
        "mma.sync.aligned.m16n8k16.row.col.f32.bf16.bf16.f32 "
        "{%0,%1,%2,%3}, {%4,%5,%6,%7}, {%8,%9}, {%0,%1,%2,%3};\n"
        : "+f"(d[0]), "+f"(d[1]), "+f"(d[2]), "+f"(d[3])
        : "r"(a[0]), "r"(a[1]), "r"(a[2]), "r"(a[3]), "r"(b0), "r"(b1));
}

__shared__ __nv_bfloat16 sGA[2][BM][40];   // A: [m][k], stride 80B (bank-clean)
__shared__ __nv_bfloat16 sGBh[2][BK][72];  // B: [k][n], stride 144B (bank-clean)
__shared__ __nv_bfloat16 sGBl[2][BK][72];

__global__ __launch_bounds__(128) void k_gemm(const float* __restrict__ bias) {
    int tid  = threadIdx.x;
    int lane = tid & 31, w = tid >> 5;
    int m0 = blockIdx.y * BM;
    int n0 = blockIdx.x * BN;
    int wm = (w >> 1) * 32;
    int wn = (w & 1) * 32;

    float acc[2][4][4];
    #pragma unroll
    for (int a = 0; a < 2; a++)
        #pragma unroll
        for (int b = 0; b < 4; b++)
            #pragma unroll
            for (int c = 0; c < 4; c++) acc[a][b][c] = 0.f;

    // load-lane mapping
    int a_row = tid >> 1;             // A: 4 chunks/row -> thread covers 2 chunks
    int a_c8  = (tid & 1) * 16;       //    cols 0/16, +8 in inner loop
    int b_row = tid >> 3;             // B: 8 chunks/row
    int b_c8  = (tid & 7) * 8;

    auto load_tiles = [&](int it, int buf) {
        int k0 = it * BK;
        cp16(&sGA[buf][a_row][a_c8],     &g_Xbf[(size_t)(m0 + a_row) * DD + k0 + a_c8]);
        cp16(&sGA[buf][a_row][a_c8 + 8], &g_Xbf[(size_t)(m0 + a_row) * DD + k0 + a_c8 + 8]);
        cp16(&sGBh[buf][b_row][b_c8],      &g_Mhi[(size_t)(k0 + b_row) * DD + n0 + b_c8]);
        cp16(&sGBh[buf][b_row + 16][b_c8], &g_Mhi[(size_t)(k0 + b_row + 16) * DD + n0 + b_c8]);
        cp16(&sGBl[buf][b_row][b_c8],      &g_Mlo[(size_t)(k0 + b_row) * DD + n0 + b_c8]);
        cp16(&sGBl[buf][b_row + 16][b_c8], &g_Mlo[(size_t)(k0 + b_row + 16) * DD + n0 + b_c8]);
    };

    load_tiles(0, 0);
    asm volatile("cp.async.commit_group;\n");

    int lm = lane & 15, lh = (lane >> 4) * 8;
    for (int it = 0; it < NIT; it++) {
        asm volatile("cp.async.wait_group 0;\n");
        __syncthreads();
        if (it + 1 < NIT) {
            load_tiles(it + 1, (it + 1) & 1);
            asm volatile("cp.async.commit_group;\n");
        }
        int buf = it & 1;
        #pragma unroll
        for (int ks = 0; ks < BK; ks += 16) {
            uint32_t af[2][4], bh[2][4], bl[2][4];
            #pragma unroll
            for (int mt = 0; mt < 2; mt++)
                ldmx4(af[mt], &sGA[buf][wm + mt * 16 + lm][ks + lh]);
            #pragma unroll
            for (int nb = 0; nb < 2; nb++) {
                ldmx4t(bh[nb], &sGBh[buf][ks + lm][wn + nb * 16 + lh]);
                ldmx4t(bl[nb], &sGBl[buf][ks + lm][wn + nb * 16 + lh]);
            }
            #pragma unroll
            for (int nt = 0; nt < 4; nt++) {
                int nb = nt >> 1, sel = (nt & 1) * 2;
                #pragma unroll
                for (int mt = 0; mt < 2; mt++) {
                    mma16816(acc[mt][nt], af[mt], bh[nb][sel], bh[nb][sel + 1]);
                    mma16816(acc[mt][nt], af[mt], bl[nb][sel], bl[nb][sel + 1]);
                }
            }
        }
        __syncthreads();
    }

    int r = lane >> 2, c2 = (lane & 3) * 2;
    #pragma unroll
    for (int mt = 0; mt < 2; mt++)
        #pragma unroll
        for (int nt = 0; nt < 4; nt++) {
            int grow = m0 + wm + mt * 16 + r;
            int gcol = n0 + wn + nt * 8 + c2;
            float b0v = bias[gcol], b1v = bias[gcol + 1];
            g_grad[(size_t)grow * DD + gcol]           = 0.5f * acc[mt][nt][0] + b0v;
            g_grad[(size_t)grow * DD + gcol + 1]       = 0.5f * acc[mt][nt][1] + b1v;
            g_grad[(size_t)(grow + 8) * DD + gcol]     = 0.5f * acc[mt][nt][2] + b0v;
            g_grad[(size_t)(grow + 8) * DD + gcol + 1] = 0.5f * acc[mt][nt][3] + b1v;
        }
}

// ---------------------------------------------------------------------------
// Kernel 4: per-row sampler, register-resident. One CTA (256 thr) per row.
// Thread t owns j = g*1024 + t*4 + e  (g<4, e<4): 16 values in registers.
// ---------------------------------------------------------------------------
__global__ __launch_bounds__(256) void k_sample(
    const float* __restrict__ x, const float* __restrict__ W,
    const int* __restrict__ radius_raw, const float* __restrict__ gum,
    const float* __restrict__ u, float* __restrict__ out)
{
    int row = blockIdx.x;
    int tid = threadIdx.x;
    int lane = tid & 31, wid = tid >> 5;

    __shared__ float s_red[8];
    __shared__ int   s_redi[8];
    __shared__ int   s_bi;
    __shared__ int   s_idx[16];
    __shared__ float s_scal[4];

    const float* xr  = x      + (size_t)row * DD;
    const float* gr  = g_grad + (size_t)row * DD;
    const float* gur = gum    + (size_t)row * DD;

    float xv[16], scx[16], key[16];
    #pragma unroll
    for (int g = 0; g < 4; g++) {
        int base = g * 1024 + tid * 4;
        float4 vx = *(const float4*)&xr[base];
        float4 vg = *(const float4*)&gr[base];
        float4 vu = *(const float4*)&gur[base];
        float fx[4] = {vx.x, vx.y, vx.z, vx.w};
        float fg[4] = {vg.x, vg.y, vg.z, vg.w};
        float fu[4] = {vu.x, vu.y, vu.z, vu.w};
        #pragma unroll
        for (int e = 0; e < 4; e++) {
            int k = g * 4 + e;
            xv[k]  = fx[e];
            scx[k] = (0.5f - fx[e]) * fg[e];
            float uu = fminf(fmaxf(fu[e], 1e-10f), 1.0f - 1e-10f);
            key[k] = scx[k] - __logf(-__logf(uu));
        }
    }

    // ---- lse_x ----
    float m = -FLT_MAX;
    #pragma unroll
    for (int k = 0; k < 16; k++) m = fmaxf(m, scx[k]);
    #pragma unroll
    for (int o = 16; o > 0; o >>= 1) m = fmaxf(m, __shfl_xor_sync(0xffffffffu, m, o));
    if (lane == 0) s_red[wid] = m;
    __syncthreads();
    float mx = s_red[0];
    #pragma unroll
    for (int ww = 1; ww < 8; ww++) mx = fmaxf(mx, s_red[ww]);
    __syncthreads();
    float s = 0.f;
    #pragma unroll
    for (int k = 0; k < 16; k++) s += __expf(scx[k] - mx);
    #pragma unroll
    for (int o = 16; o > 0; o >>= 1) s += __shfl_xor_sync(0xffffffffu, s, o);
    if (lane == 0) s_red[wid] = s;
    __syncthreads();
    float ss = 0.f;
    #pragma unroll
    for (int ww = 0; ww < 8; ww++) ss += s_red[ww];
    float lse_x = mx + logf(ss);
    __syncthreads();

    // ---- top-radius via register argmax ----
    int radius = radius_raw[row] + 1;           // [1, 15]
    for (int t = 0; t < radius; t++) {
        float bv = -FLT_MAX; int bk = 0;
        #pragma unroll
        for (int k = 0; k < 16; k++)
            if (key[k] > bv) { bv = key[k]; bk = k; }
        int bj = (bk >> 2) * 1024 + tid * 4 + (bk & 3);
        #pragma unroll
        for (int o = 16; o > 0; o >>= 1) {
            float v2 = __shfl_down_sync(0xffffffffu, bv, o);
            int   i2 = __shfl_down_sync(0xffffffffu, bj, o);
            if (v2 > bv || (v2 == bv && i2 < bj)) { bv = v2; bj = i2; }
        }
        if (lane == 0) { s_red[wid] = bv; s_redi[wid] = bj; }
        __syncthreads();
        if (tid == 0) {
            float wv = s_red[0]; int wj = s_redi[0];
            #pragma unroll
            for (int ww = 1; ww < 8; ww++) {
                float v2 = s_red[ww]; int i2 = s_redi[ww];
                if (v2 > wv || (v2 == wv && i2 < wj)) { wv = v2; wj = i2; }
            }
            s_bi = wj; s_idx[t] = wj;
        }
        __syncthreads();
        int j = s_bi;
        if (((j & 1023) >> 2) == tid) key[(j >> 10) * 4 + (j & 3)] = -FLT_MAX;
        __syncthreads();
    }

    // flip mask for this thread's 16 positions
    unsigned mask = 0;
    for (int t = 0; t < radius; t++) {
        int j = s_idx[t];
        if (((j & 1023) >> 2) == tid) mask |= 1u << ((j >> 10) * 4 + (j & 3));
    }

    // ---- quad = 0.5 * d^T W d over flipped positions ----
    float q = 0.f;
    int rr = radius * radius;
    for (int p = tid; p < rr; p += 256) {
        int a = p / radius, bb = p - a * radius;
        int ia = s_idx[a], ib = s_idx[bb];
        float da = 1.f - 2.f * xr[ia];
        float db = 1.f - 2.f * xr[ib];
        q += da * db * W[(size_t)ia * DD + ib];
    }
    #pragma unroll
    for (int o = 16; o > 0; o >>= 1) q += __shfl_xor_sync(0xffffffffu, q, o);
    __syncthreads();
    if (lane == 0) s_red[wid] = q;
    __syncthreads();
    float quad = 0.f;
    #pragma unroll
    for (int ww = 0; ww < 8; ww++) quad += s_red[ww];
    quad *= 0.5f;
    __syncthreads();

    // ---- lse_y: scx with signs flipped at mask positions ----
    float m2 = -FLT_MAX;
    #pragma unroll
    for (int k = 0; k < 16; k++) {
        float v = (mask >> k) & 1 ? -scx[k] : scx[k];
        m2 = fmaxf(m2, v);
    }
    #pragma unroll
    for (int o = 16; o > 0; o >>= 1) m2 = fmaxf(m2, __shfl_xor_sync(0xffffffffu, m2, o));
    if (lane == 0) s_red[wid] = m2;
    __syncthreads();
    float mx2 = s_red[0];
    #pragma unroll
    for (int ww = 1; ww < 8; ww++) mx2 = fmaxf(mx2, s_red[ww]);
    __syncthreads();
    float s2 = 0.f;
    #pragma unroll
    for (int k = 0; k < 16; k++) {
        float v = (mask >> k) & 1 ? -scx[k] : scx[k];
        s2 += __expf(v - mx2);
    }
    #pragma unroll
    for (int o = 16; o > 0; o >>= 1) s2 += __shfl_xor_sync(0xffffffffu, s2, o);
    if (lane == 0) s_red[wid] = s2;
    __syncthreads();
    float ss2 = 0.f;
    #pragma unroll
    for (int ww = 0; ww < 8; ww++) ss2 += s_red[ww];
    float lse_y = mx2 + logf(ss2);

    // ---- accept + write ----
    float la = fminf(quad + lse_x - lse_y, 0.f);
    int accept = (__expf(la) > u[row]) ? 1 : 0;

    float* outr = out + (size_t)row * DD;
    #pragma unroll
    for (int g = 0; g < 4; g++) {
        int base = g * 1024 + tid * 4;
        float4 o4;
        float* po = (float*)&o4;
        #pragma unroll
        for (int e = 0; e < 4; e++) {
            int k = g * 4 + e;
            float yv = ((mask >> k) & 1) ? (1.f - xv[k]) : xv[k];
            po[e] = accept ? yv : xv[k];
        }
        *(float4*)&outr[base] = o4;
    }
}

// ---------------------------------------------------------------------------
extern "C" void kernel_launch(void* const* d_in, const int* in_sizes, int n_in,
                              void* d_out, int out_size) {
    const float* x          = (const float*)d_in[0];
    const float* W          = (const float*)d_in[1];
    const float* bias       = (const float*)d_in[2];
    const int*   radius_raw = (const int*)d_in[3];
    const float* gum        = (const float*)d_in[4];
    const float* u          = (const float*)d_in[5];
    float* out = (float*)d_out;

    k_buildM<<<dim3(DD / 64, DD / 64), 256>>>(W);
    k_convX<<<(BD * DD) / 1024, 256>>>(x);
    k_gemm<<<dim3(DD / BN, BD / BM), 128>>>(bias);
    k_sample<<<BD, 256>>>(x, W, radius_raw, gum, u, out);
}

// round 6
// speedup vs baseline: 2.1058x; 1.4697x over previous
#include <cuda_runtime.h>
#include <cuda_bf16.h>
#include <math.h>
#include <float.h>
#include <stdint.h>

#define BD 256      // batch
#define DD 4096     // dim

// Scratch (allocation-free: device globals)
__device__ __nv_bfloat16 g_Mhi[(size_t)DD * DD];   // bf16 hi of W + W^T (symmetric)
__device__ __nv_bfloat16 g_Mlo[(size_t)DD * DD];   // bf16 residual (symmetric)
__device__ __nv_bfloat16 g_Xbf[(size_t)BD * DD];   // x in bf16 (exact: binary)
__device__ float         g_grad[(size_t)BD * DD];  // grad = 0.5(W+W^T)x + b

// ===========================================================================
// helpers
// ===========================================================================
__device__ __forceinline__ uint32_t smem_u32(const void* p) {
    uint32_t a;
    asm("{ .reg .u64 t; cvta.to.shared.u64 t, %1; cvt.u32.u64 %0, t; }" : "=r"(a) : "l"(p));
    return a;
}
__device__ __forceinline__ void cp16(uint32_t s, const void* g) {
    asm volatile("cp.async.cg.shared.global [%0], [%1], 16;\n" :: "r"(s), "l"(g));
}
#define CP_COMMIT() asm volatile("cp.async.commit_group;\n" ::: "memory")
#define CP_WAIT2()  asm volatile("cp.async.wait_group 2;\n" ::: "memory")

__device__ __forceinline__ void ldmx4(uint32_t* r, uint32_t a) {
    asm volatile("ldmatrix.sync.aligned.m8n8.x4.shared.b16 {%0,%1,%2,%3}, [%4];\n"
                 : "=r"(r[0]), "=r"(r[1]), "=r"(r[2]), "=r"(r[3]) : "r"(a));
}
__device__ __forceinline__ void ldmx4t(uint32_t* r, uint32_t a) {
    asm volatile("ldmatrix.sync.aligned.m8n8.x4.trans.shared.b16 {%0,%1,%2,%3}, [%4];\n"
                 : "=r"(r[0]), "=r"(r[1]), "=r"(r[2]), "=r"(r[3]) : "r"(a));
}
__device__ __forceinline__ void mma16816(float* d, const uint32_t* a, uint32_t b0, uint32_t b1) {
    asm volatile(
        "mma.sync.aligned.m16n8k16.row.col.f32.bf16.bf16.f32 "
        "{%0,%1,%2,%3}, {%4,%5,%6,%7}, {%8,%9}, {%0,%1,%2,%3};\n"
        : "+f"(d[0]), "+f"(d[1]), "+f"(d[2]), "+f"(d[3])
        : "r"(a[0]), "r"(a[1]), "r"(a[2]), "r"(a[3]), "r"(b0), "r"(b1));
}
__device__ __forceinline__ uint32_t swz(uint32_t off) {   // SW128: bits[6:4] ^= bits[9:7]
    return off ^ ((off >> 3) & 0x70);
}

// ---------------------------------------------------------------------------
// Kernel 1: M = W + W^T -> bf16 hi + bf16 lo. 64x64 tile pairs, W read once.
// ---------------------------------------------------------------------------
__global__ __launch_bounds__(256) void k_buildM(const float* __restrict__ W) {
    int bx = blockIdx.x, by = blockIdx.y;
    if (by > bx) return;
    __shared__ float t1[64][65];
    __shared__ float t2[64][65];
    int tid = threadIdx.x;
    int r1 = by * 64, c1 = bx * 64;
    bool diag = (bx == by);

    #pragma unroll
    for (int i = 0; i < 4; i++) {
        int chunk = tid + i * 256;
        int row = chunk >> 4;
        int c4  = (chunk & 15) * 4;
        float4 v1 = *(const float4*)&W[(size_t)(r1 + row) * DD + c1 + c4];
        t1[row][c4] = v1.x; t1[row][c4+1] = v1.y; t1[row][c4+2] = v1.z; t1[row][c4+3] = v1.w;
        if (!diag) {
            float4 v2 = *(const float4*)&W[(size_t)(c1 + row) * DD + r1 + c4];
            t2[row][c4] = v2.x; t2[row][c4+1] = v2.y; t2[row][c4+2] = v2.z; t2[row][c4+3] = v2.w;
        } else {
            t2[row][c4] = v1.x; t2[row][c4+1] = v1.y; t2[row][c4+2] = v1.z; t2[row][c4+3] = v1.w;
        }
    }
    __syncthreads();

    #pragma unroll
    for (int i = 0; i < 8; i++) {
        int pair = tid + i * 256;
        int row = pair >> 5;
        int cp  = pair & 31;
        {
            float a = t1[row][2*cp]   + t2[2*cp][row];
            float b = t1[row][2*cp+1] + t2[2*cp+1][row];
            size_t off = (size_t)(r1 + row) * DD + c1 + 2*cp;
            __nv_bfloat16 ha = __float2bfloat16(a), hb = __float2bfloat16(b);
            __nv_bfloat162 h; h.x = ha; h.y = hb;
            *(__nv_bfloat162*)&g_Mhi[off] = h;
            __nv_bfloat162 l;
            l.x = __float2bfloat16(a - __bfloat162float(ha));
            l.y = __float2bfloat16(b - __bfloat162float(hb));
            *(__nv_bfloat162*)&g_Mlo[off] = l;
        }
        if (!diag) {
            float a = t2[row][2*cp]   + t1[2*cp][row];
            float b = t2[row][2*cp+1] + t1[2*cp+1][row];
            size_t off = (size_t)(c1 + row) * DD + r1 + 2*cp;
            __nv_bfloat16 ha = __float2bfloat16(a), hb = __float2bfloat16(b);
            __nv_bfloat162 h; h.x = ha; h.y = hb;
            *(__nv_bfloat162*)&g_Mhi[off] = h;
            __nv_bfloat162 l;
            l.x = __float2bfloat16(a - __bfloat162float(ha));
            l.y = __float2bfloat16(b - __bfloat162float(hb));
            *(__nv_bfloat162*)&g_Mlo[off] = l;
        }
    }
}

// ---------------------------------------------------------------------------
// Kernel 2: x -> bf16 (exact: x is 0/1)
// ---------------------------------------------------------------------------
__global__ void k_convX(const float* __restrict__ x) {
    int i = (blockIdx.x * 256 + threadIdx.x) * 4;
    float4 v = *(const float4*)&x[i];
    __nv_bfloat162 p0; p0.x = __float2bfloat16(v.x); p0.y = __float2bfloat16(v.y);
    __nv_bfloat162 p1; p1.x = __float2bfloat16(v.z); p1.y = __float2bfloat16(v.w);
    *(__nv_bfloat162*)&g_Xbf[i]     = p0;
    *(__nv_bfloat162*)&g_Xbf[i + 2] = p1;
}

// ---------------------------------------------------------------------------
// Kernel 3: GEMM  grad = 0.5 * (Xbf @ Mhi + Xbf @ Mlo) + bias
// BM=BN=64, BK=64, 4-stage cp.async pipeline (prefetch distance 3), SW128
// swizzled smem (no padding), one __syncthreads per K-iter.
// B tile uses symmetry: B[k][n] = M[k0+k][n0+n] read as plain rows.
// Grid (64, 4) = 256 CTAs, 128 threads.
// ---------------------------------------------------------------------------
#define TM 64
#define TN 64
#define TKK 64
#define GST 4
#define GNIT (DD / TKK)          // 64
#define GTILE 8192               // 64 rows x 128B
#define GSTAGE_B (3 * GTILE)     // A + Bh + Bl = 24KB
#define GSMEM (GST * GSTAGE_B + 1024)

extern __shared__ char g_dynsm[];

__global__ __launch_bounds__(128) void k_gemm(const float* __restrict__ bias) {
    int tid  = threadIdx.x;
    int lane = tid & 31, w = tid >> 5;
    int m0 = blockIdx.y * TM;
    int n0 = blockIdx.x * TN;
    int wm = (w >> 1) * 32;
    int wn = (w & 1) * 32;

    uint32_t base = (smem_u32(g_dynsm) + 1023u) & ~1023u;

    float acc[2][4][4];
    #pragma unroll
    for (int a = 0; a < 2; a++)
        #pragma unroll
        for (int b = 0; b < 4; b++)
            #pragma unroll
            for (int c = 0; c < 4; c++) acc[a][b][c] = 0.f;

    // loader mapping: 512 16B-chunks per 64x128B tile, 4 per thread
    const __nv_bfloat16* gA = g_Xbf + (size_t)m0 * DD;
    const __nv_bfloat16* gH = g_Mhi + (size_t)n0;
    const __nv_bfloat16* gL = g_Mlo + (size_t)n0;

    auto load_stage = [&](int s, int it) {
        int k0 = it * TKK;
        uint32_t sb = base + s * GSTAGE_B;
        #pragma unroll
        for (int i = 0; i < 4; i++) {
            int id  = tid + i * 128;
            int row = id >> 3;
            int ce  = (id & 7) * 8;           // element col
            uint32_t d = swz((uint32_t)(row * 128 + ce * 2));
            cp16(sb + d,              gA + (size_t)row * DD + k0 + ce);           // A[m][k]
            cp16(sb + GTILE + d,      gH + (size_t)(k0 + row) * DD + ce);         // Bh[k][n]
            cp16(sb + 2 * GTILE + d,  gL + (size_t)(k0 + row) * DD + ce);         // Bl[k][n]
        }
    };

    #pragma unroll
    for (int s = 0; s < 3; s++) { load_stage(s, s); CP_COMMIT(); }

    int lm = lane & 15, lh = (lane >> 4) * 8;

    for (int it = 0; it < GNIT; it++) {
        int s = it & 3;
        CP_WAIT2();
        __syncthreads();
        if (it + 3 < GNIT) load_stage((it + 3) & 3, it + 3);
        CP_COMMIT();

        uint32_t sbA = base + s * GSTAGE_B;
        uint32_t sbH = sbA + GTILE;
        uint32_t sbL = sbA + 2 * GTILE;

        #pragma unroll
        for (int ks = 0; ks < TKK; ks += 16) {
            uint32_t af[2][4], bh[2][4], bl[2][4];
            #pragma unroll
            for (int mt = 0; mt < 2; mt++) {
                uint32_t byte = (uint32_t)((wm + mt * 16 + lm) * 128 + (ks + lh) * 2);
                ldmx4(af[mt], sbA + swz(byte));
            }
            #pragma unroll
            for (int nb = 0; nb < 2; nb++) {
                uint32_t byte = (uint32_t)((ks + lm) * 128 + (wn + nb * 16 + lh) * 2);
                ldmx4t(bh[nb], sbH + swz(byte));
                ldmx4t(bl[nb], sbL + swz(byte));
            }
            #pragma unroll
            for (int nt = 0; nt < 4; nt++) {
                int nb = nt >> 1, sel = (nt & 1) * 2;
                #pragma unroll
                for (int mt = 0; mt < 2; mt++) {
                    mma16816(acc[mt][nt], af[mt], bh[nb][sel], bh[nb][sel + 1]);
                    mma16816(acc[mt][nt], af[mt], bl[nb][sel], bl[nb][sel + 1]);
                }
            }
        }
    }

    int r = lane >> 2, c2 = (lane & 3) * 2;
    #pragma unroll
    for (int mt = 0; mt < 2; mt++)
        #pragma unroll
        for (int nt = 0; nt < 4; nt++) {
            int grow = m0 + wm + mt * 16 + r;
            int gcol = n0 + wn + nt * 8 + c2;
            float b0v = bias[gcol], b1v = bias[gcol + 1];
            g_grad[(size_t)grow * DD + gcol]           = 0.5f * acc[mt][nt][0] + b0v;
            g_grad[(size_t)grow * DD + gcol + 1]       = 0.5f * acc[mt][nt][1] + b1v;
            g_grad[(size_t)(grow + 8) * DD + gcol]     = 0.5f * acc[mt][nt][2] + b0v;
            g_grad[(size_t)(grow + 8) * DD + gcol + 1] = 0.5f * acc[mt][nt][3] + b1v;
        }
}

// ---------------------------------------------------------------------------
// Kernel 4: per-row sampler, register-resident. One CTA (512 thr) per row.
// Thread t owns j = g*2048 + t*4 + e  (g<2, e<4): 8 values in registers.
// ---------------------------------------------------------------------------
#define ST 512
#define NW (ST / 32)

__global__ __launch_bounds__(ST) void k_sample(
    const float* __restrict__ x, const float* __restrict__ W,
    const int* __restrict__ radius_raw, const float* __restrict__ gum,
    const float* __restrict__ u, float* __restrict__ out)
{
    int row = blockIdx.x;
    int tid = threadIdx.x;
    int lane = tid & 31, wid = tid >> 5;

    __shared__ float s_red[NW];
    __shared__ int   s_redi[NW];
    __shared__ int   s_bi;
    __shared__ int   s_idx[16];

    const float* xr  = x      + (size_t)row * DD;
    const float* gr  = g_grad + (size_t)row * DD;
    const float* gur = gum    + (size_t)row * DD;

    float xv[8], scx[8], key[8];
    #pragma unroll
    for (int g = 0; g < 2; g++) {
        int base = g * 2048 + tid * 4;
        float4 vx = *(const float4*)&xr[base];
        float4 vg = *(const float4*)&gr[base];
        float4 vu = *(const float4*)&gur[base];
        float fx[4] = {vx.x, vx.y, vx.z, vx.w};
        float fg[4] = {vg.x, vg.y, vg.z, vg.w};
        float fu[4] = {vu.x, vu.y, vu.z, vu.w};
        #pragma unroll
        for (int e = 0; e < 4; e++) {
            int k = g * 4 + e;
            xv[k]  = fx[e];
            scx[k] = (0.5f - fx[e]) * fg[e];
            float uu = fminf(fmaxf(fu[e], 1e-10f), 1.0f - 1e-10f);
            key[k] = scx[k] - __logf(-__logf(uu));
        }
    }

    // ---- lse_x ----
    float m = -FLT_MAX;
    #pragma unroll
    for (int k = 0; k < 8; k++) m = fmaxf(m, scx[k]);
    #pragma unroll
    for (int o = 16; o > 0; o >>= 1) m = fmaxf(m, __shfl_xor_sync(0xffffffffu, m, o));
    if (lane == 0) s_red[wid] = m;
    __syncthreads();
    float mx = s_red[0];
    #pragma unroll
    for (int ww = 1; ww < NW; ww++) mx = fmaxf(mx, s_red[ww]);
    __syncthreads();
    float s = 0.f;
    #pragma unroll
    for (int k = 0; k < 8; k++) s += __expf(scx[k] - mx);
    #pragma unroll
    for (int o = 16; o > 0; o >>= 1) s += __shfl_xor_sync(0xffffffffu, s, o);
    if (lane == 0) s_red[wid] = s;
    __syncthreads();
    float ss = 0.f;
    #pragma unroll
    for (int ww = 0; ww < NW; ww++) ss += s_red[ww];
    float lse_x = mx + logf(ss);
    __syncthreads();

    // ---- top-radius via register argmax ----
    int radius = radius_raw[row] + 1;
    for (int t = 0; t < radius; t++) {
        float bv = -FLT_MAX; int bk = 0;
        #pragma unroll
        for (int k = 0; k < 8; k++)
            if (key[k] > bv) { bv = key[k]; bk = k; }
        int bj = (bk >> 2) * 2048 + tid * 4 + (bk & 3);
        #pragma unroll
        for (int o = 16; o > 0; o >>= 1) {
            float v2 = __shfl_down_sync(0xffffffffu, bv, o);
            int   i2 = __shfl_down_sync(0xffffffffu, bj, o);
            if (v2 > bv || (v2 == bv && i2 < bj)) { bv = v2; bj = i2; }
        }
        if (lane == 0) { s_red[wid] = bv; s_redi[wid] = bj; }
        __syncthreads();
        if (tid == 0) {
            float wv = s_red[0]; int wj = s_redi[0];
            #pragma unroll
            for (int ww = 1; ww < NW; ww++) {
                float v2 = s_red[ww]; int i2 = s_redi[ww];
                if (v2 > wv || (v2 == wv && i2 < wj)) { wv = v2; wj = i2; }
            }
            s_bi = wj; s_idx[t] = wj;
        }
        __syncthreads();
        int j = s_bi;
        if (((j & 2047) >> 2) == tid) key[(j >> 11) * 4 + (j & 3)] = -FLT_MAX;
        __syncthreads();
    }

    unsigned mask = 0;
    for (int t = 0; t < radius; t++) {
        int j = s_idx[t];
        if (((j & 2047) >> 2) == tid) mask |= 1u << ((j >> 11) * 4 + (j & 3));
    }

    // ---- quad = 0.5 * d^T W d over flipped positions ----
    float q = 0.f;
    int rr = radius * radius;
    for (int p = tid; p < rr; p += ST) {
        int a = p / radius, bb = p - a * radius;
        int ia = s_idx[a], ib = s_idx[bb];
        float da = 1.f - 2.f * xr[ia];
        float db = 1.f - 2.f * xr[ib];
        q += da * db * W[(size_t)ia * DD + ib];
    }
    #pragma unroll
    for (int o = 16; o > 0; o >>= 1) q += __shfl_xor_sync(0xffffffffu, q, o);
    __syncthreads();
    if (lane == 0) s_red[wid] = q;
    __syncthreads();
    float quad = 0.f;
    #pragma unroll
    for (int ww = 0; ww < NW; ww++) quad += s_red[ww];
    quad *= 0.5f;
    __syncthreads();

    // ---- lse_y ----
    float m2 = -FLT_MAX;
    #pragma unroll
    for (int k = 0; k < 8; k++) {
        float v = (mask >> k) & 1 ? -scx[k] : scx[k];
        m2 = fmaxf(m2, v);
    }
    #pragma unroll
    for (int o = 16; o > 0; o >>= 1) m2 = fmaxf(m2, __shfl_xor_sync(0xffffffffu, m2, o));
    if (lane == 0) s_red[wid] = m2;
    __syncthreads();
    float mx2 = s_red[0];
    #pragma unroll
    for (int ww = 1; ww < NW; ww++) mx2 = fmaxf(mx2, s_red[ww]);
    __syncthreads();
    float s2 = 0.f;
    #pragma unroll
    for (int k = 0; k < 8; k++) {
        float v = (mask >> k) & 1 ? -scx[k] : scx[k];
        s2 += __expf(v - mx2);
    }
    #pragma unroll
    for (int o = 16; o > 0; o >>= 1) s2 += __shfl_xor_sync(0xffffffffu, s2, o);
    if (lane == 0) s_red[wid] = s2;
    __syncthreads();
    float ss2 = 0.f;
    #pragma unroll
    for (int ww = 0; ww < NW; ww++) ss2 += s_red[ww];
    float lse_y = mx2 + logf(ss2);

    // ---- accept + write ----
    float la = fminf(quad + lse_x - lse_y, 0.f);
    int accept = (__expf(la) > u[row]) ? 1 : 0;

    float* outr = out + (size_t)row * DD;
    #pragma unroll
    for (int g = 0; g < 2; g++) {
        int base = g * 2048 + tid * 4;
        float4 o4;
        float* po = (float*)&o4;
        #pragma unroll
        for (int e = 0; e < 4; e++) {
            int k = g * 4 + e;
            float yv = ((mask >> k) & 1) ? (1.f - xv[k]) : xv[k];
            po[e] = accept ? yv : xv[k];
        }
        *(float4*)&outr[base] = o4;
    }
}

// ---------------------------------------------------------------------------
extern "C" void kernel_launch(void* const* d_in, const int* in_sizes, int n_in,
                              void* d_out, int out_size) {
    const float* x          = (const float*)d_in[0];
    const float* W          = (const float*)d_in[1];
    const float* bias       = (const float*)d_in[2];
    const int*   radius_raw = (const int*)d_in[3];
    const float* gum        = (const float*)d_in[4];
    const float* u          = (const float*)d_in[5];
    float* out = (float*)d_out;

    // idempotent, called every launch (deterministic)
    cudaFuncSetAttribute(k_gemm, cudaFuncAttributeMaxDynamicSharedMemorySize, GSMEM);

    k_buildM<<<dim3(DD / 64, DD / 64), 256>>>(W);
    k_convX<<<(BD * DD) / 1024, 256>>>(x);
    k_gemm<<<dim3(DD / TN, BD / TM), 128, GSMEM>>>(bias);
    k_sample<<<BD, ST>>>(x, W, radius_raw, gum, u, out);
}

// round 7
// speedup vs baseline: 2.2451x; 1.0662x over previous
#include <cuda_runtime.h>
#include <cuda_bf16.h>
#include <math.h>
#include <float.h>
#include <stdint.h>

#define BD 256      // batch
#define DD 4096     // dim

// Scratch (allocation-free: device globals)
__device__ __nv_bfloat16 g_Mhi[(size_t)DD * DD];   // bf16 hi of W + W^T (symmetric)
__device__ __nv_bfloat16 g_Mlo[(size_t)DD * DD];   // bf16 residual (symmetric)
__device__ __nv_bfloat16 g_Xbf[(size_t)BD * DD];   // x in bf16 (exact: binary)
__device__ float         g_grad[(size_t)BD * DD];  // grad = 0.5(W+W^T)x + b

// ===========================================================================
// helpers
// ===========================================================================
__device__ __forceinline__ uint32_t smem_u32(const void* p) {
    uint32_t a;
    asm("{ .reg .u64 t; cvta.to.shared.u64 t, %1; cvt.u32.u64 %0, t; }" : "=r"(a) : "l"(p));
    return a;
}
__device__ __forceinline__ void cp16(uint32_t s, const void* g) {
    asm volatile("cp.async.cg.shared.global [%0], [%1], 16;\n" :: "r"(s), "l"(g));
}
#define CP_COMMIT() asm volatile("cp.async.commit_group;\n" ::: "memory")
#define CP_WAIT2()  asm volatile("cp.async.wait_group 2;\n" ::: "memory")

__device__ __forceinline__ void ldmx4(uint32_t* r, uint32_t a) {
    asm volatile("ldmatrix.sync.aligned.m8n8.x4.shared.b16 {%0,%1,%2,%3}, [%4];\n"
                 : "=r"(r[0]), "=r"(r[1]), "=r"(r[2]), "=r"(r[3]) : "r"(a));
}
__device__ __forceinline__ void ldmx4t(uint32_t* r, uint32_t a) {
    asm volatile("ldmatrix.sync.aligned.m8n8.x4.trans.shared.b16 {%0,%1,%2,%3}, [%4];\n"
                 : "=r"(r[0]), "=r"(r[1]), "=r"(r[2]), "=r"(r[3]) : "r"(a));
}
__device__ __forceinline__ void mma16816(float* d, const uint32_t* a, uint32_t b0, uint32_t b1) {
    asm volatile(
        "mma.sync.aligned.m16n8k16.row.col.f32.bf16.bf16.f32 "
        "{%0,%1,%2,%3}, {%4,%5,%6,%7}, {%8,%9}, {%0,%1,%2,%3};\n"
        : "+f"(d[0]), "+f"(d[1]), "+f"(d[2]), "+f"(d[3])
        : "r"(a[0]), "r"(a[1]), "r"(a[2]), "r"(a[3]), "r"(b0), "r"(b1));
}
__device__ __forceinline__ uint32_t swz(uint32_t off) {   // SW128: bits[6:4] ^= bits[9:7]
    return off ^ ((off >> 3) & 0x70);
}

// ---------------------------------------------------------------------------
// Kernel 1: M = W + W^T -> bf16 hi + bf16 lo. 64x64 tile pairs, W read once.
// Phase 2 uses 16B packed stores (full-width store transactions).
// ---------------------------------------------------------------------------
__global__ __launch_bounds__(256) void k_buildM(const float* __restrict__ W) {
    int bx = blockIdx.x, by = blockIdx.y;
    if (by > bx) return;
    __shared__ float t1[64][65];
    __shared__ float t2[64][65];
    int tid = threadIdx.x;
    int r1 = by * 64, c1 = bx * 64;
    bool diag = (bx == by);

    #pragma unroll
    for (int i = 0; i < 4; i++) {
        int chunk = tid + i * 256;
        int row = chunk >> 4;
        int c4  = (chunk & 15) * 4;
        float4 v1 = *(const float4*)&W[(size_t)(r1 + row) * DD + c1 + c4];
        t1[row][c4] = v1.x; t1[row][c4+1] = v1.y; t1[row][c4+2] = v1.z; t1[row][c4+3] = v1.w;
        if (!diag) {
            float4 v2 = *(const float4*)&W[(size_t)(c1 + row) * DD + r1 + c4];
            t2[row][c4] = v2.x; t2[row][c4+1] = v2.y; t2[row][c4+2] = v2.z; t2[row][c4+3] = v2.w;
        } else {
            t2[row][c4] = v1.x; t2[row][c4+1] = v1.y; t2[row][c4+2] = v1.z; t2[row][c4+3] = v1.w;
        }
    }
    __syncthreads();

    #pragma unroll
    for (int i = 0; i < 2; i++) {
        int u   = tid + i * 256;      // 0..511
        int row = u >> 3;             // 64 rows
        int cg  = (u & 7) * 8;        // 8-col group
        {
            __align__(16) __nv_bfloat16 hi[8], lo[8];
            #pragma unroll
            for (int e = 0; e < 8; e++) {
                float a = t1[row][cg + e] + t2[cg + e][row];
                __nv_bfloat16 h = __float2bfloat16(a);
                hi[e] = h;
                lo[e] = __float2bfloat16(a - __bfloat162float(h));
            }
            size_t off = (size_t)(r1 + row) * DD + c1 + cg;
            *(uint4*)&g_Mhi[off] = *(uint4*)hi;
            *(uint4*)&g_Mlo[off] = *(uint4*)lo;
        }
        if (!diag) {
            __align__(16) __nv_bfloat16 hi[8], lo[8];
            #pragma unroll
            for (int e = 0; e < 8; e++) {
                float a = t2[row][cg + e] + t1[cg + e][row];
                __nv_bfloat16 h = __float2bfloat16(a);
                hi[e] = h;
                lo[e] = __float2bfloat16(a - __bfloat162float(h));
            }
            size_t off = (size_t)(c1 + row) * DD + r1 + cg;
            *(uint4*)&g_Mhi[off] = *(uint4*)hi;
            *(uint4*)&g_Mlo[off] = *(uint4*)lo;
        }
    }
}

// ---------------------------------------------------------------------------
// Kernel 2: x -> bf16 (exact: x is 0/1)
// ---------------------------------------------------------------------------
__global__ void k_convX(const float* __restrict__ x) {
    int i = (blockIdx.x * 256 + threadIdx.x) * 4;
    float4 v = *(const float4*)&x[i];
    __nv_bfloat162 p0; p0.x = __float2bfloat16(v.x); p0.y = __float2bfloat16(v.y);
    __nv_bfloat162 p1; p1.x = __float2bfloat16(v.z); p1.y = __float2bfloat16(v.w);
    *(__nv_bfloat162*)&g_Xbf[i]     = p0;
    *(__nv_bfloat162*)&g_Xbf[i + 2] = p1;
}

// ---------------------------------------------------------------------------
// Kernel 3: GEMM  grad = 0.5 * (Xbf @ Mhi + Xbf @ Mlo) + bias
// (unchanged from R6 — verified at ~49us)
// ---------------------------------------------------------------------------
#define TM 64
#define TN 64
#define TKK 64
#define GST 4
#define GNIT (DD / TKK)          // 64
#define GTILE 8192               // 64 rows x 128B
#define GSTAGE_B (3 * GTILE)     // A + Bh + Bl = 24KB
#define GSMEM (GST * GSTAGE_B + 1024)

extern __shared__ char g_dynsm[];

__global__ __launch_bounds__(128) void k_gemm(const float* __restrict__ bias) {
    int tid  = threadIdx.x;
    int lane = tid & 31, w = tid >> 5;
    int m0 = blockIdx.y * TM;
    int n0 = blockIdx.x * TN;
    int wm = (w >> 1) * 32;
    int wn = (w & 1) * 32;

    uint32_t base = (smem_u32(g_dynsm) + 1023u) & ~1023u;

    float acc[2][4][4];
    #pragma unroll
    for (int a = 0; a < 2; a++)
        #pragma unroll
        for (int b = 0; b < 4; b++)
            #pragma unroll
            for (int c = 0; c < 4; c++) acc[a][b][c] = 0.f;

    const __nv_bfloat16* gA = g_Xbf + (size_t)m0 * DD;
    const __nv_bfloat16* gH = g_Mhi + (size_t)n0;
    const __nv_bfloat16* gL = g_Mlo + (size_t)n0;

    auto load_stage = [&](int s, int it) {
        int k0 = it * TKK;
        uint32_t sb = base + s * GSTAGE_B;
        #pragma unroll
        for (int i = 0; i < 4; i++) {
            int id  = tid + i * 128;
            int row = id >> 3;
            int ce  = (id & 7) * 8;
            uint32_t d = swz((uint32_t)(row * 128 + ce * 2));
            cp16(sb + d,              gA + (size_t)row * DD + k0 + ce);
            cp16(sb + GTILE + d,      gH + (size_t)(k0 + row) * DD + ce);
            cp16(sb + 2 * GTILE + d,  gL + (size_t)(k0 + row) * DD + ce);
        }
    };

    #pragma unroll
    for (int s = 0; s < 3; s++) { load_stage(s, s); CP_COMMIT(); }

    int lm = lane & 15, lh = (lane >> 4) * 8;

    for (int it = 0; it < GNIT; it++) {
        int s = it & 3;
        CP_WAIT2();
        __syncthreads();
        if (it + 3 < GNIT) load_stage((it + 3) & 3, it + 3);
        CP_COMMIT();

        uint32_t sbA = base + s * GSTAGE_B;
        uint32_t sbH = sbA + GTILE;
        uint32_t sbL = sbA + 2 * GTILE;

        #pragma unroll
        for (int ks = 0; ks < TKK; ks += 16) {
            uint32_t af[2][4], bh[2][4], bl[2][4];
            #pragma unroll
            for (int mt = 0; mt < 2; mt++) {
                uint32_t byte = (uint32_t)((wm + mt * 16 + lm) * 128 + (ks + lh) * 2);
                ldmx4(af[mt], sbA + swz(byte));
            }
            #pragma unroll
            for (int nb = 0; nb < 2; nb++) {
                uint32_t byte = (uint32_t)((ks + lm) * 128 + (wn + nb * 16 + lh) * 2);
                ldmx4t(bh[nb], sbH + swz(byte));
                ldmx4t(bl[nb], sbL + swz(byte));
            }
            #pragma unroll
            for (int nt = 0; nt < 4; nt++) {
                int nb = nt >> 1, sel = (nt & 1) * 2;
                #pragma unroll
                for (int mt = 0; mt < 2; mt++) {
                    mma16816(acc[mt][nt], af[mt], bh[nb][sel], bh[nb][sel + 1]);
                    mma16816(acc[mt][nt], af[mt], bl[nb][sel], bl[nb][sel + 1]);
                }
            }
        }
    }

    int r = lane >> 2, c2 = (lane & 3) * 2;
    #pragma unroll
    for (int mt = 0; mt < 2; mt++)
        #pragma unroll
        for (int nt = 0; nt < 4; nt++) {
            int grow = m0 + wm + mt * 16 + r;
            int gcol = n0 + wn + nt * 8 + c2;
            float b0v = bias[gcol], b1v = bias[gcol + 1];
            g_grad[(size_t)grow * DD + gcol]           = 0.5f * acc[mt][nt][0] + b0v;
            g_grad[(size_t)grow * DD + gcol + 1]       = 0.5f * acc[mt][nt][1] + b1v;
            g_grad[(size_t)(grow + 8) * DD + gcol]     = 0.5f * acc[mt][nt][2] + b0v;
            g_grad[(size_t)(grow + 8) * DD + gcol + 1] = 0.5f * acc[mt][nt][3] + b1v;
        }
}

// ---------------------------------------------------------------------------
// Kernel 4: per-row sampler. 256 threads/CTA, 16 values/thread in registers.
// Top-k: per-warp candidates cached in smem; each iteration tid0 merges 8
// candidates, then ONLY the winning warp invalidates + rescans (2 barriers).
// Thread t owns j = g*1024 + t*4 + e  (g<4, e<4).
// ---------------------------------------------------------------------------
#define ST 256
#define NW (ST / 32)

__global__ __launch_bounds__(ST) void k_sample(
    const float* __restrict__ x, const float* __restrict__ W,
    const int* __restrict__ radius_raw, const float* __restrict__ gum,
    const float* __restrict__ u, float* __restrict__ out)
{
    int row = blockIdx.x;
    int tid = threadIdx.x;
    int lane = tid & 31, wid = tid >> 5;

    __shared__ float s_wval[NW];
    __shared__ int   s_widx[NW];
    __shared__ float s_red[NW];
    __shared__ int   s_win;
    __shared__ int   s_idx[16];

    const float* xr  = x      + (size_t)row * DD;
    const float* gr  = g_grad + (size_t)row * DD;
    const float* gur = gum    + (size_t)row * DD;

    // ---- all loads up front (MLP 12) ----
    float4 vx[4], vg[4], vu[4];
    #pragma unroll
    for (int g = 0; g < 4; g++) vx[g] = *(const float4*)&xr[g * 1024 + tid * 4];
    #pragma unroll
    for (int g = 0; g < 4; g++) vg[g] = *(const float4*)&gr[g * 1024 + tid * 4];
    #pragma unroll
    for (int g = 0; g < 4; g++) vu[g] = *(const float4*)&gur[g * 1024 + tid * 4];

    float xv[16], scx[16], key[16];
    #pragma unroll
    for (int g = 0; g < 4; g++) {
        float fx[4] = {vx[g].x, vx[g].y, vx[g].z, vx[g].w};
        float fg[4] = {vg[g].x, vg[g].y, vg[g].z, vg[g].w};
        float fu[4] = {vu[g].x, vu[g].y, vu[g].z, vu[g].w};
        #pragma unroll
        for (int e = 0; e < 4; e++) {
            int k = g * 4 + e;
            xv[k]  = fx[e];
            scx[k] = (0.5f - fx[e]) * fg[e];
            float uu = fminf(fmaxf(fu[e], 1e-10f), 1.0f - 1e-10f);
            key[k] = scx[k] - __logf(-__logf(uu));
        }
    }

    // ---- lse_x ----
    float m = -FLT_MAX;
    #pragma unroll
    for (int k = 0; k < 16; k++) m = fmaxf(m, scx[k]);
    #pragma unroll
    for (int o = 16; o > 0; o >>= 1) m = fmaxf(m, __shfl_xor_sync(0xffffffffu, m, o));
    if (lane == 0) s_red[wid] = m;
    __syncthreads();
    float mx = s_red[0];
    #pragma unroll
    for (int ww = 1; ww < NW; ww++) mx = fmaxf(mx, s_red[ww]);
    __syncthreads();
    float s = 0.f;
    #pragma unroll
    for (int k = 0; k < 16; k++) s += __expf(scx[k] - mx);
    #pragma unroll
    for (int o = 16; o > 0; o >>= 1) s += __shfl_xor_sync(0xffffffffu, s, o);
    if (lane == 0) s_red[wid] = s;
    __syncthreads();
    float ss = 0.f;
    #pragma unroll
    for (int ww = 0; ww < NW; ww++) ss += s_red[ww];
    float lse_x = mx + logf(ss);

    // ---- initial per-warp candidate ----
    {
        float bv = -FLT_MAX; int bk = 0;
        #pragma unroll
        for (int k = 0; k < 16; k++)
            if (key[k] > bv) { bv = key[k]; bk = k; }
        int bj = (bk >> 2) * 1024 + tid * 4 + (bk & 3);
        #pragma unroll
        for (int o = 16; o > 0; o >>= 1) {
            float v2 = __shfl_down_sync(0xffffffffu, bv, o);
            int   i2 = __shfl_down_sync(0xffffffffu, bj, o);
            if (v2 > bv || (v2 == bv && i2 < bj)) { bv = v2; bj = i2; }
        }
        if (lane == 0) { s_wval[wid] = bv; s_widx[wid] = bj; }
    }
    __syncthreads();

    // ---- top-radius: 2 barriers/iter, winner-warp-only rescan ----
    int radius = radius_raw[row] + 1;          // [1, 15]
    for (int t = 0; t < radius; t++) {
        if (tid == 0) {
            float wv = s_wval[0]; int wj = s_widx[0]; int wwin = 0;
            #pragma unroll
            for (int ww = 1; ww < NW; ww++) {
                float v2 = s_wval[ww]; int i2 = s_widx[ww];
                if (v2 > wv || (v2 == wv && i2 < wj)) { wv = v2; wj = i2; wwin = ww; }
            }
            s_idx[t] = wj; s_win = wwin;
        }
        __syncthreads();
        if (wid == s_win && t + 1 < radius) {
            int j = s_idx[t];
            if (((j & 1023) >> 2) == tid) key[(j >> 10) * 4 + (j & 3)] = -FLT_MAX;
            float bv = -FLT_MAX; int bk = 0;
            #pragma unroll
            for (int k = 0; k < 16; k++)
                if (key[k] > bv) { bv = key[k]; bk = k; }
            int bj = (bk >> 2) * 1024 + tid * 4 + (bk & 3);
            #pragma unroll
            for (int o = 16; o > 0; o >>= 1) {
                float v2 = __shfl_down_sync(0xffffffffu, bv, o);
                int   i2 = __shfl_down_sync(0xffffffffu, bj, o);
                if (v2 > bv || (v2 == bv && i2 < bj)) { bv = v2; bj = i2; }
            }
            if (lane == 0) { s_wval[wid] = bv; s_widx[wid] = bj; }
        }
        __syncthreads();
    }

    // flip mask over this thread's 16 positions
    unsigned mask = 0;
    for (int t = 0; t < radius; t++) {
        int j = s_idx[t];
        if (((j & 1023) >> 2) == tid) mask |= 1u << ((j >> 10) * 4 + (j & 3));
    }

    // ---- quad = 0.5 * d^T W d over flipped positions ----
    float q = 0.f;
    int rr = radius * radius;
    for (int p = tid; p < rr; p += ST) {
        int a = p / radius, bb = p - a * radius;
        int ia = s_idx[a], ib = s_idx[bb];
        float da = 1.f - 2.f * xr[ia];
        float db = 1.f - 2.f * xr[ib];
        q += da * db * W[(size_t)ia * DD + ib];
    }
    #pragma unroll
    for (int o = 16; o > 0; o >>= 1) q += __shfl_xor_sync(0xffffffffu, q, o);
    __syncthreads();
    if (lane == 0) s_red[wid] = q;
    __syncthreads();
    float quad = 0.f;
    #pragma unroll
    for (int ww = 0; ww < NW; ww++) quad += s_red[ww];
    quad *= 0.5f;
    __syncthreads();

    // ---- lse_y ----
    float m2 = -FLT_MAX;
    #pragma unroll
    for (int k = 0; k < 16; k++) {
        float v = (mask >> k) & 1 ? -scx[k] : scx[k];
        m2 = fmaxf(m2, v);
    }
    #pragma unroll
    for (int o = 16; o > 0; o >>= 1) m2 = fmaxf(m2, __shfl_xor_sync(0xffffffffu, m2, o));
    if (lane == 0) s_red[wid] = m2;
    __syncthreads();
    float mx2 = s_red[0];
    #pragma unroll
    for (int ww = 1; ww < NW; ww++) mx2 = fmaxf(mx2, s_red[ww]);
    __syncthreads();
    float s2 = 0.f;
    #pragma unroll
    for (int k = 0; k < 16; k++) {
        float v = (mask >> k) & 1 ? -scx[k] : scx[k];
        s2 += __expf(v - mx2);
    }
    #pragma unroll
    for (int o = 16; o > 0; o >>= 1) s2 += __shfl_xor_sync(0xffffffffu, s2, o);
    if (lane == 0) s_red[wid] = s2;
    __syncthreads();
    float ss2 = 0.f;
    #pragma unroll
    for (int ww = 0; ww < NW; ww++) ss2 += s_red[ww];
    float lse_y = mx2 + logf(ss2);

    // ---- accept + write ----
    float la = fminf(quad + lse_x - lse_y, 0.f);
    int accept = (__expf(la) > u[row]) ? 1 : 0;

    float* outr = out + (size_t)row * DD;
    #pragma unroll
    for (int g = 0; g < 4; g++) {
        int base = g * 1024 + tid * 4;
        float4 o4;
        float* po = (float*)&o4;
        #pragma unroll
        for (int e = 0; e < 4; e++) {
            int k = g * 4 + e;
            float yv = ((mask >> k) & 1) ? (1.f - xv[k]) : xv[k];
            po[e] = accept ? yv : xv[k];
        }
        *(float4*)&outr[base] = o4;
    }
}

// ---------------------------------------------------------------------------
extern "C" void kernel_launch(void* const* d_in, const int* in_sizes, int n_in,
                              void* d_out, int out_size) {
    const float* x          = (const float*)d_in[0];
    const float* W          = (const float*)d_in[1];
    const float* bias       = (const float*)d_in[2];
    const int*   radius_raw = (const int*)d_in[3];
    const float* gum        = (const float*)d_in[4];
    const float* u          = (const float*)d_in[5];
    float* out = (float*)d_out;

    cudaFuncSetAttribute(k_gemm, cudaFuncAttributeMaxDynamicSharedMemorySize, GSMEM);

    k_buildM<<<dim3(DD / 64, DD / 64), 256>>>(W);
    k_convX<<<(BD * DD) / 1024, 256>>>(x);
    k_gemm<<<dim3(DD / TN, BD / TM), 128, GSMEM>>>(bias);
    k_sample<<<BD, ST>>>(x, W, radius_raw, gum, u, out);
}